// round 4
// baseline (speedup 1.0000x reference)
#include <cuda_runtime.h>
#include <cuda_fp16.h>

// Problem constants (fixed by the reference)
#define B_  8
#define N_  2048
#define L_  2048
#define Q_  512
#define D_  512
#define NH_ 4
#define TL_ 32   // l-tile per block

// fp16 copy of the 4 embedding tables (4 * 512 * 512 * 2B = 2 MiB).
// Static __device__ scratch (no allocation in kernel_launch).
__device__ __align__(128) __half g_emb[NH_ * Q_ * D_];

// ---------------------------------------------------------------------------
// Kernel 1: convert emb0..emb3 (f32) -> fp16 table. 131072 threads, 8 elems ea.
// ---------------------------------------------------------------------------
__global__ void convert_emb_kernel(const float* __restrict__ e0,
                                   const float* __restrict__ e1,
                                   const float* __restrict__ e2,
                                   const float* __restrict__ e3) {
    int i = blockIdx.x * blockDim.x + threadIdx.x;   // 0 .. 131071
    const int per = Q_ * D_ / 8;                      // 32768 per head
    int h = i >> 15;                                  // i / per
    int o = (i & (per - 1)) * 8;
    const float* src = (h == 0) ? e0 : (h == 1) ? e1 : (h == 2) ? e2 : e3;
    const float4* s = reinterpret_cast<const float4*>(src + o);
    float4 a = s[0];
    float4 b = s[1];
    __half2* dst = reinterpret_cast<__half2*>(g_emb + h * (Q_ * D_) + o);
    dst[0] = __floats2half2_rn(a.x, a.y);
    dst[1] = __floats2half2_rn(a.z, a.w);
    dst[2] = __floats2half2_rn(b.x, b.y);
    dst[3] = __floats2half2_rn(b.z, b.w);
}

// ---------------------------------------------------------------------------
// Kernel 2: fused top-3 + softmax + gather-combine.
// Block = (b, 32-l tile), 128 threads (4 warps).
// Phase A: warp = head, lane = l. Phase B: warp = dd slab of 128, lane = l.
// ---------------------------------------------------------------------------
__global__ __launch_bounds__(128)
void embed_fused_kernel(const float* __restrict__ logits,
                        float* __restrict__ out) {
    const int blk = blockIdx.x;          // 0 .. 511
    const int b   = blk >> 6;            // blk / (L_/TL_)
    const int lt  = blk & 63;
    const int l0  = lt * TL_;

    __shared__ float s_w[NH_][TL_][3];
    __shared__ short s_i[NH_][TL_][3];

    const int tid  = threadIdx.x;
    const int wid  = tid >> 5;           // warp id (= head in phase A)
    const int lane = tid & 31;

    // -------------------- Phase A: top-3 over codebook dim --------------------
    {
        const int h = wid;
        // logits[b][h*Q + j][l0 + lane], stride L_ along j; warp-coalesced in l.
        const float* lp = logits + (size_t)b * N_ * L_ + (size_t)h * Q_ * L_
                                 + l0 + lane;
        float v0 = -1e30f, v1 = -1e30f, v2 = -1e30f;
        int   i0 = 0, i1 = 0, i2 = 0;
        #pragma unroll 4
        for (int j = 0; j < Q_; ++j) {
            float v = __ldcs(lp + (size_t)j * L_);   // streaming: protect L2 for emb
            if (v > v2) {
                if (v > v1) {
                    v2 = v1; i2 = i1;
                    if (v > v0) { v1 = v0; i1 = i0; v0 = v; i0 = j; }
                    else        { v1 = v;  i1 = j; }
                } else {
                    v2 = v; i2 = j;
                }
            }
        }
        // softmax over the 3 top values (max = v0)
        float e1e = __expf(v1 - v0);
        float e2e = __expf(v2 - v0);
        float inv = 1.0f / (1.0f + e1e + e2e);
        s_w[h][lane][0] = inv;
        s_w[h][lane][1] = e1e * inv;
        s_w[h][lane][2] = e2e * inv;
        s_i[h][lane][0] = (short)i0;
        s_i[h][lane][1] = (short)i1;
        s_i[h][lane][2] = (short)i2;
    }
    __syncthreads();

    // -------------------- Phase B: gather-combine --------------------
    // This lane owns l = l0 + lane; this warp owns dd in [wid*128, wid*128+128).
    float wt[12];
    int   off[12];
    #pragma unroll
    for (int h = 0; h < NH_; ++h) {
        #pragma unroll
        for (int k = 0; k < 3; ++k) {
            wt[h * 3 + k]  = s_w[h][lane][k];
            off[h * 3 + k] = (h * Q_ + (int)s_i[h][lane][k]) * D_;
        }
    }

    float* outp = out + (size_t)b * D_ * L_ + l0 + lane;

    #pragma unroll
    for (int c = 0; c < 4; ++c) {                 // 4 chunks of 32 dd
        const int dd0 = wid * 128 + c * 32;
        float acc[32];
        #pragma unroll
        for (int i = 0; i < 32; ++i) acc[i] = 0.0f;

        #pragma unroll
        for (int t = 0; t < 12; ++t) {
            const float w = wt[t];
            const uint4* p =
                reinterpret_cast<const uint4*>(g_emb + off[t] + dd0);
            #pragma unroll
            for (int u = 0; u < 4; ++u) {         // 4 x LDG.128 = 32 halves
                uint4 raw = p[u];
                unsigned rr[4] = {raw.x, raw.y, raw.z, raw.w};
                #pragma unroll
                for (int q = 0; q < 4; ++q) {
                    __half2 hv = *reinterpret_cast<__half2*>(&rr[q]);
                    float2  f  = __half22float2(hv);
                    acc[u * 8 + q * 2]     += w * f.x;
                    acc[u * 8 + q * 2 + 1] += w * f.y;
                }
            }
        }
        // out[b][dd0+i][l] — lanes along l => 128B-coalesced stores
        #pragma unroll
        for (int i = 0; i < 32; ++i) {
            __stcs(outp + (size_t)(dd0 + i) * L_, acc[i]);
        }
    }
}

// ---------------------------------------------------------------------------
extern "C" void kernel_launch(void* const* d_in, const int* in_sizes, int n_in,
                              void* d_out, int out_size) {
    (void)in_sizes; (void)n_in; (void)out_size;
    const float* logits = (const float*)d_in[0];
    const float* e0 = (const float*)d_in[1];
    const float* e1 = (const float*)d_in[2];
    const float* e2 = (const float*)d_in[3];
    const float* e3 = (const float*)d_in[4];
    float* out = (float*)d_out;

    convert_emb_kernel<<<512, 256>>>(e0, e1, e2, e3);
    embed_fused_kernel<<<B_ * (L_ / TL_), 128>>>(logits, out);
}

// round 7
// speedup vs baseline: 2.1024x; 2.1024x over previous
#include <cuda_runtime.h>
#include <cuda_fp16.h>

// Problem constants (fixed by the reference)
#define B_  8
#define N_  2048
#define L_  2048
#define Q_  512
#define D_  512
#define NH_ 4
#define TL_ 32   // l-tile per block

// fp16 copy of the 4 embedding tables (4 * 512 * 512 * 2B = 2 MiB).
__device__ __align__(128) __half g_emb[NH_ * Q_ * D_];
// Scratch: per (b,h,l): w0,w1,w2 (float) + packed indices (int as float). 1 MiB.
__device__ __align__(128) float4 g_scr[B_ * NH_ * L_];

// ---------------------------------------------------------------------------
// Kernel 1: convert emb0..emb3 (f32) -> fp16 table.
// ---------------------------------------------------------------------------
__global__ void convert_emb_kernel(const float* __restrict__ e0,
                                   const float* __restrict__ e1,
                                   const float* __restrict__ e2,
                                   const float* __restrict__ e3) {
    int i = blockIdx.x * blockDim.x + threadIdx.x;   // 0 .. 131071
    const int per = Q_ * D_ / 8;                      // 32768 per head
    int h = i >> 15;
    int o = (i & (per - 1)) * 8;
    const float* src = (h == 0) ? e0 : (h == 1) ? e1 : (h == 2) ? e2 : e3;
    const float4* s = reinterpret_cast<const float4*>(src + o);
    float4 a = s[0];
    float4 b = s[1];
    __half2* dst = reinterpret_cast<__half2*>(g_emb + h * (Q_ * D_) + o);
    dst[0] = __floats2half2_rn(a.x, a.y);
    dst[1] = __floats2half2_rn(a.z, a.w);
    dst[2] = __floats2half2_rn(b.x, b.y);
    dst[3] = __floats2half2_rn(b.z, b.w);
}

// ---------------------------------------------------------------------------
// Branch-free exact top-3 insert (stable: equal values keep the earlier index,
// matching jax.lax.top_k's lower-index-first tie break).
// ---------------------------------------------------------------------------
__device__ __forceinline__ void top3_insert(float v, int j,
                                            float& v0, float& v1, float& v2,
                                            int& i0, int& i1, int& i2) {
    bool g2 = v > v2;
    bool g1 = v > v1;
    bool g0 = v > v0;
    v2 = g1 ? v1 : (g2 ? v : v2);
    i2 = g1 ? i1 : (g2 ? j : i2);
    v1 = g0 ? v0 : (g1 ? v : v1);
    i1 = g0 ? i0 : (g1 ? j : i1);
    v0 = g0 ? v : v0;
    i0 = g0 ? j : i0;
}

// ---------------------------------------------------------------------------
// Kernel 2: top-3 + softmax -> scratch.
// Block = (b, h, 32-l tile), 128 threads. Warp w scans j in [w*128, w*128+128),
// lane = l (coalesced 128B line per warp load). smem merge of 4 partial lists.
// ---------------------------------------------------------------------------
__global__ __launch_bounds__(128)
void topk_kernel(const float* __restrict__ logits) {
    const int x  = blockIdx.x;           // 0 .. 2047
    const int b  = x >> 8;
    const int h  = (x >> 6) & 3;
    const int lt = x & 63;
    const int l0 = lt * TL_;

    const int wid  = threadIdx.x >> 5;
    const int lane = threadIdx.x & 31;

    const float* lp = logits + ((size_t)b * N_ + h * Q_ + wid * 128) * L_
                             + l0 + lane;

    float v0 = -1e30f, v1 = -1e30f, v2 = -1e30f;
    int   i0 = 0, i1 = 0, i2 = 0;
    const int jbase = wid * 128;
    #pragma unroll 8
    for (int j = 0; j < 128; ++j) {
        float v = __ldcs(lp + (size_t)j * L_);   // streaming: keep L2 for emb
        top3_insert(v, jbase + j, v0, v1, v2, i0, i1, i2);
    }

    __shared__ float sv[4][TL_][3];
    __shared__ short si[4][TL_][3];
    sv[wid][lane][0] = v0; sv[wid][lane][1] = v1; sv[wid][lane][2] = v2;
    si[wid][lane][0] = (short)i0; si[wid][lane][1] = (short)i1;
    si[wid][lane][2] = (short)i2;
    __syncthreads();

    if (wid == 0) {
        float m0 = -1e30f, m1 = -1e30f, m2 = -1e30f;
        int   j0 = 0, j1 = 0, j2 = 0;
        #pragma unroll
        for (int s = 0; s < 4; ++s) {
            #pragma unroll
            for (int k = 0; k < 3; ++k) {
                top3_insert(sv[s][lane][k], (int)si[s][lane][k],
                            m0, m1, m2, j0, j1, j2);
            }
        }
        float e1 = __expf(m1 - m0);
        float e2 = __expf(m2 - m0);
        float inv = 1.0f / (1.0f + e1 + e2);
        int packed = j0 | (j1 << 10) | (j2 << 20);
        g_scr[((b * NH_ + h) << 11) + l0 + lane] =
            make_float4(inv, e1 * inv, e2 * inv, __int_as_float(packed));
    }
}

// ---------------------------------------------------------------------------
// Kernel 3: gather-combine.
// Block = (b, 32-l tile, 128-d chunk), 128 threads.
// Loads: lane = d (coalesced 256B row-chunk reads from L2-resident fp16 table).
// Transpose via padded smem, stores coalesced along l.
// ---------------------------------------------------------------------------
__global__ __launch_bounds__(128)
void gather_kernel(float* __restrict__ out) {
    const int x  = blockIdx.x;           // 0 .. 2047
    const int b  = x >> 8;
    const int lt = (x >> 2) & 63;
    const int dc = x & 3;
    const int l0 = lt * TL_;
    const int d0 = dc * 128;

    __shared__ float s_w[NH_ * TL_ * 3];
    __shared__ int   s_off[NH_ * TL_ * 3];
    __shared__ float s_t[TL_][129];      // transpose buffer, padded

    const int tid  = threadIdx.x;
    const int wid  = tid >> 5;
    const int lane = tid & 31;

    // Load scratch for the 32 l's x 4 heads (one float4 per thread).
    {
        const int h = tid >> 5;          // 0..3
        const int l = tid & 31;
        float4 sc = g_scr[((b * NH_ + h) << 11) + l0 + l];
        int packed = __float_as_int(sc.w);
        int base = (h * TL_ + l) * 3;
        s_w[base + 0] = sc.x;
        s_w[base + 1] = sc.y;
        s_w[base + 2] = sc.z;
        s_off[base + 0] = ((h << 9) + (packed         & 1023)) * D_ + d0;
        s_off[base + 1] = ((h << 9) + ((packed >> 10) & 1023)) * D_ + d0;
        s_off[base + 2] = ((h << 9) + ((packed >> 20) & 1023)) * D_ + d0;
    }
    __syncthreads();

    // Each warp processes 8 l's; per l: 12 coalesced row-chunk loads.
    #pragma unroll 2
    for (int li = 0; li < 8; ++li) {
        const int l = wid * 8 + li;
        float a0 = 0.f, a1 = 0.f, a2 = 0.f, a3 = 0.f;
        #pragma unroll
        for (int t = 0; t < 12; ++t) {
            const int h = t / 3, k = t - h * 3;
            const int base = (h * TL_ + l) * 3 + k;
            const float w  = s_w[base];
            const int  off = s_off[base];
            uint2 r = *reinterpret_cast<const uint2*>(g_emb + off + lane * 4);
            __half2 ha = *reinterpret_cast<__half2*>(&r.x);
            __half2 hb = *reinterpret_cast<__half2*>(&r.y);
            float2 fa = __half22float2(ha);
            float2 fb = __half22float2(hb);
            a0 += w * fa.x; a1 += w * fa.y;
            a2 += w * fb.x; a3 += w * fb.y;
        }
        s_t[l][lane * 4 + 0] = a0;
        s_t[l][lane * 4 + 1] = a1;
        s_t[l][lane * 4 + 2] = a2;
        s_t[l][lane * 4 + 3] = a3;
    }
    __syncthreads();

    // Store: out[b][d0+dd][l0+lane], lanes along l -> 128B-coalesced.
    float* op = out + ((size_t)b * D_ + d0) * L_ + l0 + lane;
    #pragma unroll 8
    for (int i = 0; i < 32; ++i) {
        const int dd = wid * 32 + i;
        __stcs(op + (size_t)dd * L_, s_t[lane][dd]);
    }
}

// ---------------------------------------------------------------------------
extern "C" void kernel_launch(void* const* d_in, const int* in_sizes, int n_in,
                              void* d_out, int out_size) {
    (void)in_sizes; (void)n_in; (void)out_size;
    const float* logits = (const float*)d_in[0];
    const float* e0 = (const float*)d_in[1];
    const float* e1 = (const float*)d_in[2];
    const float* e2 = (const float*)d_in[3];
    const float* e3 = (const float*)d_in[4];
    float* out = (float*)d_out;

    convert_emb_kernel<<<512, 256>>>(e0, e1, e2, e3);
    topk_kernel<<<B_ * NH_ * (L_ / TL_), 128>>>(logits);
    gather_kernel<<<B_ * (L_ / TL_) * (D_ / 128), 128>>>(out);
}

// round 11
// speedup vs baseline: 2.1410x; 1.0183x over previous
#include <cuda_runtime.h>
#include <cuda_fp16.h>

// Problem constants (fixed by the reference)
#define B_  8
#define N_  2048
#define L_  2048
#define Q_  512
#define D_  512
#define NH_ 4
#define TL_ 32   // l-tile per block

// fp16 copy of the 4 embedding tables (4 * 512 * 512 * 2B = 2 MiB).
__device__ __align__(128) __half g_emb[NH_ * Q_ * D_];
// Scratch: per (b,h,l): w0,w1,w2 (float) + packed indices (int as float). 1 MiB.
__device__ __align__(128) float4 g_scr[B_ * NH_ * L_];

// ---------------------------------------------------------------------------
// Branch-free exact top-3 insert (stable: equal values keep the earlier index,
// matching jax.lax.top_k's lower-index-first tie break).
// ---------------------------------------------------------------------------
__device__ __forceinline__ void top3_insert(float v, int j,
                                            float& v0, float& v1, float& v2,
                                            int& i0, int& i1, int& i2) {
    bool g2 = v > v2;
    bool g1 = v > v1;
    bool g0 = v > v0;
    v2 = g1 ? v1 : (g2 ? v : v2);
    i2 = g1 ? i1 : (g2 ? j : i2);
    v1 = g0 ? v0 : (g1 ? v : v1);
    i1 = g0 ? i0 : (g1 ? j : i1);
    v0 = g0 ? v : v0;
    i0 = g0 ? j : i0;
}

// ---------------------------------------------------------------------------
// Kernel 1: fused [emb f32->fp16 convert prologue] + [top-3 + softmax].
// Block = (b, h, 32-l tile), 128 threads.
// Prologue: 2048 blocks x 128 thr x 4 elems = 1,048,576 = exactly the table.
// Topk: warp w scans j in [w*128, w*128+128), lane = l (coalesced 128B line
// per warp load). smem merge of 4 partial top-3 lists.
// ---------------------------------------------------------------------------
__global__ __launch_bounds__(128)
void topk_kernel(const float* __restrict__ logits,
                 const float* __restrict__ e0,
                 const float* __restrict__ e1,
                 const float* __restrict__ e2,
                 const float* __restrict__ e3) {
    // ---- convert prologue ----
    {
        int base = blockIdx.x * 512 + threadIdx.x * 4;   // < 1,048,576
        int h = base >> 18;                               // 262144 elems/head
        int o = base & 262143;
        const float* src = (h == 0) ? e0 : (h == 1) ? e1 : (h == 2) ? e2 : e3;
        float4 a = *reinterpret_cast<const float4*>(src + o);
        __half2 h0 = __floats2half2_rn(a.x, a.y);
        __half2 h1 = __floats2half2_rn(a.z, a.w);
        uint2 packed;
        packed.x = *reinterpret_cast<unsigned*>(&h0);
        packed.y = *reinterpret_cast<unsigned*>(&h1);
        *reinterpret_cast<uint2*>(g_emb + base) = packed;
    }

    // ---- top-3 ----
    const int x  = blockIdx.x;           // 0 .. 2047
    const int b  = x >> 8;
    const int h  = (x >> 6) & 3;
    const int lt = x & 63;
    const int l0 = lt * TL_;

    const int wid  = threadIdx.x >> 5;
    const int lane = threadIdx.x & 31;

    const float* lp = logits + ((size_t)b * N_ + h * Q_ + wid * 128) * L_
                             + l0 + lane;

    float v0 = -1e30f, v1 = -1e30f, v2 = -1e30f;
    int   i0 = 0, i1 = 0, i2 = 0;
    const int jbase = wid * 128;
    #pragma unroll 8
    for (int j = 0; j < 128; ++j) {
        float v = __ldcs(lp + (size_t)j * L_);   // streaming: keep L2 for emb
        top3_insert(v, jbase + j, v0, v1, v2, i0, i1, i2);
    }

    __shared__ float sv[4][TL_][3];
    __shared__ short si[4][TL_][3];
    sv[wid][lane][0] = v0; sv[wid][lane][1] = v1; sv[wid][lane][2] = v2;
    si[wid][lane][0] = (short)i0; si[wid][lane][1] = (short)i1;
    si[wid][lane][2] = (short)i2;
    __syncthreads();

    if (wid == 0) {
        float m0 = -1e30f, m1 = -1e30f, m2 = -1e30f;
        int   j0 = 0, j1 = 0, j2 = 0;
        #pragma unroll
        for (int s = 0; s < 4; ++s) {
            #pragma unroll
            for (int k = 0; k < 3; ++k) {
                top3_insert(sv[s][lane][k], (int)si[s][lane][k],
                            m0, m1, m2, j0, j1, j2);
            }
        }
        float e1v = __expf(m1 - m0);
        float e2v = __expf(m2 - m0);
        float inv = 1.0f / (1.0f + e1v + e2v);
        int packed = j0 | (j1 << 10) | (j2 << 20);
        g_scr[((b * NH_ + h) << 11) + l0 + lane] =
            make_float4(inv, e1v * inv, e2v * inv, __int_as_float(packed));
    }
}

// ---------------------------------------------------------------------------
// Kernel 2: gather-combine.
// Block = (b, 32-l tile, 256-d chunk), 128 threads. Grid = 8*64*2 = 1024.
// Loads: per (l, term) one warp-coalesced LDG.128 sweep (32 lanes x uint4 =
// 512B = the full 256-half row chunk). Transpose via padded smem (258 floats
// per row: float2-aligned writes), stores 128B-coalesced along l.
// ---------------------------------------------------------------------------
__global__ __launch_bounds__(128)
void gather_kernel(float* __restrict__ out) {
    const int x  = blockIdx.x;           // 0 .. 1023
    const int b  = x >> 7;
    const int lt = (x >> 1) & 63;
    const int dc = x & 1;
    const int l0 = lt * TL_;
    const int d0 = dc * 256;

    __shared__ float s_w[NH_ * TL_ * 3];
    __shared__ int   s_off[NH_ * TL_ * 3];
    __shared__ float s_t[TL_][258];      // transpose buffer (row = l)

    const int tid  = threadIdx.x;
    const int wid  = tid >> 5;
    const int lane = tid & 31;

    // Load scratch for the 32 l's x 4 heads (one float4 per thread).
    {
        const int h = tid >> 5;          // 0..3
        const int l = tid & 31;
        float4 sc = g_scr[((b * NH_ + h) << 11) + l0 + l];
        int packed = __float_as_int(sc.w);
        int base = (h * TL_ + l) * 3;
        s_w[base + 0] = sc.x;
        s_w[base + 1] = sc.y;
        s_w[base + 2] = sc.z;
        s_off[base + 0] = ((h << 9) + (packed         & 1023)) * D_ + d0;
        s_off[base + 1] = ((h << 9) + ((packed >> 10) & 1023)) * D_ + d0;
        s_off[base + 2] = ((h << 9) + ((packed >> 20) & 1023)) * D_ + d0;
    }
    __syncthreads();

    // Each warp processes 8 l's; per l: 12 LDG.128 row-chunk loads (512B each).
    #pragma unroll 2
    for (int li = 0; li < 8; ++li) {
        const int l = wid * 8 + li;
        float acc[8];
        #pragma unroll
        for (int i = 0; i < 8; ++i) acc[i] = 0.0f;

        #pragma unroll
        for (int t = 0; t < 12; ++t) {
            const int h = t / 3, k = t - h * 3;
            const int base = (h * TL_ + l) * 3 + k;
            const float w  = s_w[base];
            const int  off = s_off[base];
            uint4 r = *reinterpret_cast<const uint4*>(g_emb + off + lane * 8);
            unsigned rr[4] = {r.x, r.y, r.z, r.w};
            #pragma unroll
            for (int q = 0; q < 4; ++q) {
                __half2 hv = *reinterpret_cast<__half2*>(&rr[q]);
                float2  f  = __half22float2(hv);
                acc[q * 2]     += w * f.x;
                acc[q * 2 + 1] += w * f.y;
            }
        }
        // s_t[l][lane*8 + q]: float2 writes (row stride 258 -> 8B aligned)
        float2* row = reinterpret_cast<float2*>(&s_t[l][lane * 8]);
        row[0] = make_float2(acc[0], acc[1]);
        row[1] = make_float2(acc[2], acc[3]);
        row[2] = make_float2(acc[4], acc[5]);
        row[3] = make_float2(acc[6], acc[7]);
    }
    __syncthreads();

    // Store: out[b][d0+dd][l0+lane], lanes along l -> 128B-coalesced.
    float* op = out + ((size_t)b * D_ + d0) * L_ + l0 + lane;
    #pragma unroll 8
    for (int i = 0; i < 64; ++i) {
        const int dd = wid * 64 + i;
        __stcs(op + (size_t)dd * L_, s_t[lane][dd]);
    }
}

// ---------------------------------------------------------------------------
extern "C" void kernel_launch(void* const* d_in, const int* in_sizes, int n_in,
                              void* d_out, int out_size) {
    (void)in_sizes; (void)n_in; (void)out_size;
    const float* logits = (const float*)d_in[0];
    const float* e0 = (const float*)d_in[1];
    const float* e1 = (const float*)d_in[2];
    const float* e2 = (const float*)d_in[3];
    const float* e3 = (const float*)d_in[4];
    float* out = (float*)d_out;

    topk_kernel<<<B_ * NH_ * (L_ / TL_), 128>>>(logits, e0, e1, e2, e3);
    gather_kernel<<<B_ * (L_ / TL_) * (D_ / 256), 128>>>(out);
}

// round 12
// speedup vs baseline: 2.4315x; 1.1357x over previous
#include <cuda_runtime.h>
#include <cuda_fp16.h>

// Problem constants (fixed by the reference)
#define B_  8
#define N_  2048
#define L_  2048
#define Q_  512
#define D_  512
#define NH_ 4
#define TL_  32   // l-tile for topk blocks
#define TLG_ 16   // l-tile for gather blocks

// fp16 copy of the 4 embedding tables (4 * 512 * 512 * 2B = 2 MiB).
__device__ __align__(128) __half g_emb[NH_ * Q_ * D_];
// Scratch: per (b,h,l): w0,w1,w2 (float) + packed indices (int as float). 1 MiB.
__device__ __align__(128) float4 g_scr[B_ * NH_ * L_];

// ---------------------------------------------------------------------------
// Branch-free exact top-3 insert (stable: equal values keep the earlier index,
// matching jax.lax.top_k's lower-index-first tie break).
// ---------------------------------------------------------------------------
__device__ __forceinline__ void top3_insert(float v, int j,
                                            float& v0, float& v1, float& v2,
                                            int& i0, int& i1, int& i2) {
    bool g2 = v > v2;
    bool g1 = v > v1;
    bool g0 = v > v0;
    v2 = g1 ? v1 : (g2 ? v : v2);
    i2 = g1 ? i1 : (g2 ? j : i2);
    v1 = g0 ? v0 : (g1 ? v : v1);
    i1 = g0 ? i0 : (g1 ? j : i1);
    v0 = g0 ? v : v0;
    i0 = g0 ? j : i0;
}

// ---------------------------------------------------------------------------
// Kernel 1: fused [emb f32->fp16 convert prologue] + [top-3 + softmax].
// Block = (b, h, 32-l tile), 128 threads.
// Prologue: 2048 blocks x 128 thr x 4 elems = 1,048,576 = exactly the table.
// Topk: warp w scans j in [w*128, w*128+128), lane = l. Software-pipelined:
// chunk of 16 values double-buffered so the next chunk's 16 LDGs are in
// flight while the select chains of the current chunk issue.
// ---------------------------------------------------------------------------
__global__ __launch_bounds__(128)
void topk_kernel(const float* __restrict__ logits,
                 const float* __restrict__ e0,
                 const float* __restrict__ e1,
                 const float* __restrict__ e2,
                 const float* __restrict__ e3) {
    // ---- convert prologue ----
    {
        int base = blockIdx.x * 512 + threadIdx.x * 4;   // < 1,048,576
        int h = base >> 18;                               // 262144 elems/head
        int o = base & 262143;
        const float* src = (h == 0) ? e0 : (h == 1) ? e1 : (h == 2) ? e2 : e3;
        float4 a = *reinterpret_cast<const float4*>(src + o);
        __half2 h0 = __floats2half2_rn(a.x, a.y);
        __half2 h1 = __floats2half2_rn(a.z, a.w);
        uint2 packed;
        packed.x = *reinterpret_cast<unsigned*>(&h0);
        packed.y = *reinterpret_cast<unsigned*>(&h1);
        *reinterpret_cast<uint2*>(g_emb + base) = packed;
    }

    // ---- top-3, software-pipelined ----
    const int x  = blockIdx.x;           // 0 .. 2047
    const int b  = x >> 8;
    const int h  = (x >> 6) & 3;
    const int lt = x & 63;
    const int l0 = lt * TL_;

    const int wid  = threadIdx.x >> 5;
    const int lane = threadIdx.x & 31;

    const float* lp = logits + ((size_t)b * N_ + h * Q_ + wid * 128) * L_
                             + l0 + lane;

    float v0 = -1e30f, v1 = -1e30f, v2 = -1e30f;
    int   i0 = 0, i1 = 0, i2 = 0;
    const int jbase = wid * 128;

    float cur[16];
    #pragma unroll
    for (int u = 0; u < 16; ++u)
        cur[u] = __ldcs(lp + (size_t)u * L_);

    #pragma unroll
    for (int c = 0; c < 8; ++c) {        // 8 chunks of 16 = 128 elements
        float nxt[16];
        if (c < 7) {
            #pragma unroll
            for (int u = 0; u < 16; ++u)
                nxt[u] = __ldcs(lp + (size_t)((c + 1) * 16 + u) * L_);
        }
        #pragma unroll
        for (int u = 0; u < 16; ++u)
            top3_insert(cur[u], jbase + c * 16 + u, v0, v1, v2, i0, i1, i2);
        if (c < 7) {
            #pragma unroll
            for (int u = 0; u < 16; ++u) cur[u] = nxt[u];
        }
    }

    __shared__ float sv[4][TL_][3];
    __shared__ short si[4][TL_][3];
    sv[wid][lane][0] = v0; sv[wid][lane][1] = v1; sv[wid][lane][2] = v2;
    si[wid][lane][0] = (short)i0; si[wid][lane][1] = (short)i1;
    si[wid][lane][2] = (short)i2;
    __syncthreads();

    if (wid == 0) {
        float m0 = -1e30f, m1 = -1e30f, m2 = -1e30f;
        int   j0 = 0, j1 = 0, j2 = 0;
        #pragma unroll
        for (int s = 0; s < 4; ++s) {
            #pragma unroll
            for (int k = 0; k < 3; ++k) {
                top3_insert(sv[s][lane][k], (int)si[s][lane][k],
                            m0, m1, m2, j0, j1, j2);
            }
        }
        float e1v = __expf(m1 - m0);
        float e2v = __expf(m2 - m0);
        float inv = 1.0f / (1.0f + e1v + e2v);
        int packed = j0 | (j1 << 10) | (j2 << 20);
        g_scr[((b * NH_ + h) << 11) + l0 + lane] =
            make_float4(inv, e1v * inv, e2v * inv, __int_as_float(packed));
    }
}

// ---------------------------------------------------------------------------
// Kernel 2: gather-combine.
// Block = (b, 16-l tile, 256-d chunk), 128 threads. Grid = 8*128*2 = 2048.
// Smaller 16-l tile halves the transpose buffer (16x258 floats = 16.5KB) so
// occupancy rises from 30% to ~50%. Loads: per (l, term) one warp-coalesced
// LDG.128 sweep (512B). Stores 64B-coalesced along l (sector-complete).
// ---------------------------------------------------------------------------
__global__ __launch_bounds__(128)
void gather_kernel(float* __restrict__ out) {
    const int x  = blockIdx.x;           // 0 .. 2047
    const int b  = x >> 8;
    const int lt = (x >> 1) & 127;
    const int dc = x & 1;
    const int l0 = lt * TLG_;
    const int d0 = dc * 256;

    __shared__ float s_w[NH_ * TLG_ * 3];
    __shared__ int   s_off[NH_ * TLG_ * 3];
    __shared__ float s_t[TLG_][258];     // transpose buffer (row = l)

    const int tid  = threadIdx.x;
    const int wid  = tid >> 5;
    const int lane = tid & 31;

    // Load scratch for the 16 l's x 4 heads (64 float4's, first 64 threads).
    if (tid < NH_ * TLG_) {
        const int h = tid >> 4;          // 0..3
        const int l = tid & 15;
        float4 sc = g_scr[((b * NH_ + h) << 11) + l0 + l];
        int packed = __float_as_int(sc.w);
        int base = (h * TLG_ + l) * 3;
        s_w[base + 0] = sc.x;
        s_w[base + 1] = sc.y;
        s_w[base + 2] = sc.z;
        s_off[base + 0] = ((h << 9) + (packed         & 1023)) * D_ + d0;
        s_off[base + 1] = ((h << 9) + ((packed >> 10) & 1023)) * D_ + d0;
        s_off[base + 2] = ((h << 9) + ((packed >> 20) & 1023)) * D_ + d0;
    }
    __syncthreads();

    // Each warp processes 4 l's; per l: 12 LDG.128 row-chunk loads (512B each).
    #pragma unroll 2
    for (int li = 0; li < 4; ++li) {
        const int l = wid * 4 + li;
        float acc[8];
        #pragma unroll
        for (int i = 0; i < 8; ++i) acc[i] = 0.0f;

        #pragma unroll
        for (int t = 0; t < 12; ++t) {
            const int h = t / 3, k = t - h * 3;
            const int base = (h * TLG_ + l) * 3 + k;
            const float w  = s_w[base];
            const int  off = s_off[base];
            uint4 r = *reinterpret_cast<const uint4*>(g_emb + off + lane * 8);
            unsigned rr[4] = {r.x, r.y, r.z, r.w};
            #pragma unroll
            for (int q = 0; q < 4; ++q) {
                __half2 hv = *reinterpret_cast<__half2*>(&rr[q]);
                float2  f  = __half22float2(hv);
                acc[q * 2]     += w * f.x;
                acc[q * 2 + 1] += w * f.y;
            }
        }
        float2* row = reinterpret_cast<float2*>(&s_t[l][lane * 8]);
        row[0] = make_float2(acc[0], acc[1]);
        row[1] = make_float2(acc[2], acc[3]);
        row[2] = make_float2(acc[4], acc[5]);
        row[3] = make_float2(acc[6], acc[7]);
    }
    __syncthreads();

    // Store: out[b][d0+dd][l0+lc], 16 consecutive lc per dd row (64B runs,
    // sector-complete). Thread (r, lc): r = tid>>4 in 0..7, lc = tid&15.
    const int r  = tid >> 4;
    const int lc = tid & 15;
    float* op = out + ((size_t)b * D_ + d0) * L_ + l0 + lc;
    #pragma unroll 8
    for (int i = 0; i < 32; ++i) {
        const int dd = r * 32 + i;
        __stcs(op + (size_t)dd * L_, s_t[lc][dd]);
    }
}

// ---------------------------------------------------------------------------
extern "C" void kernel_launch(void* const* d_in, const int* in_sizes, int n_in,
                              void* d_out, int out_size) {
    (void)in_sizes; (void)n_in; (void)out_size;
    const float* logits = (const float*)d_in[0];
    const float* e0 = (const float*)d_in[1];
    const float* e1 = (const float*)d_in[2];
    const float* e2 = (const float*)d_in[3];
    const float* e3 = (const float*)d_in[4];
    float* out = (float*)d_out;

    topk_kernel<<<B_ * NH_ * (L_ / TL_), 128>>>(logits, e0, e1, e2, e3);
    gather_kernel<<<B_ * (L_ / TLG_) * (D_ / 256), 128>>>(out);
}